// round 1
// baseline (speedup 1.0000x reference)
#include <cuda_runtime.h>

#define NN 4096
#define MM 2048
#define DD 1024
#define ITERS 100
#define SINK_BLOCKS 148
#define SINK_THREADS 1024

// ---------------- static scratch (no allocations allowed) ----------------
__device__ float d_xs[NN * DD];     // shifted x
__device__ float d_ys[MM * DD];     // shifted y
__device__ float d_xn[NN];          // row sq-norms of shifted x
__device__ float d_yn[MM];
__device__ float d_C[NN * MM];      // cost matrix (fp32, 33.5MB)
__device__ float d_Km[NN * MM];     // Gibbs kernel  (fp32, 33.5MB)
__device__ float d_u[NN];
__device__ float d_v[MM];
__device__ float d_KTu[MM];
__device__ int d_cmax_bits;
__device__ unsigned int d_bar_arrive;
__device__ unsigned int d_bar_release;
__device__ double d_dist;

// ---------------- init: reset all cross-launch state (graph-replay safe) ----------------
__global__ void init_kernel() {
    int j = blockIdx.x * blockDim.x + threadIdx.x;
    if (j < MM) {
        d_v[j]   = 1.0f / MM;   // v0 = 1/m
        d_KTu[j] = 0.0f;
    }
    if (j == 0) {
        d_cmax_bits   = 0;
        d_bar_arrive  = 0;
        d_bar_release = 0;
        d_dist        = 0.0;
    }
}

// ---------------- row-min shift + squared norms ----------------
__global__ __launch_bounds__(256) void prep_kernel(const float* __restrict__ x,
                                                   const float* __restrict__ y) {
    __shared__ float red[256];
    int b = blockIdx.x;
    const float* src;
    float* dst;
    float* nrm;
    int row;
    if (b < NN) { row = b;       src = x + (size_t)row * DD; dst = d_xs + (size_t)row * DD; nrm = d_xn; }
    else        { row = b - NN;  src = y + (size_t)row * DD; dst = d_ys + (size_t)row * DD; nrm = d_yn; }

    int tid = threadIdx.x;
    float vals[4];
    float vmin = 3.4e38f;
#pragma unroll
    for (int i = 0; i < 4; i++) {
        vals[i] = src[tid + i * 256];
        vmin = fminf(vmin, vals[i]);
    }
    red[tid] = vmin;
    __syncthreads();
    for (int s = 128; s > 0; s >>= 1) {
        if (tid < s) red[tid] = fminf(red[tid], red[tid + s]);
        __syncthreads();
    }
    vmin = red[0];
    __syncthreads();

    float ss = 0.0f;
#pragma unroll
    for (int i = 0; i < 4; i++) {
        float t = vals[i] - vmin;
        dst[tid + i * 256] = t;
        ss += t * t;
    }
    red[tid] = ss;
    __syncthreads();
    for (int s = 128; s > 0; s >>= 1) {
        if (tid < s) red[tid] += red[tid + s];
        __syncthreads();
    }
    if (tid == 0) nrm[row] = red[0];
}

// ---------------- fp32 SGEMM (G = xs @ ys^T) fused with C = max(xn+yn-2G, 0) + global max ----------------
__global__ __launch_bounds__(256) void gemm_cost_kernel() {
    __shared__ float As[8][128];
    __shared__ float Bs[8][128];
    __shared__ float redm[256];

    int j0 = blockIdx.x * 128;  // M dim
    int i0 = blockIdx.y * 128;  // N dim
    int tid = threadIdx.x;
    int tx = tid & 15, ty = tid >> 4;
    int lrow = tid >> 1;
    int lseg = (tid & 1) * 4;

    const float* Ab = d_xs + (size_t)(i0 + lrow) * DD + lseg;
    const float* Bb = d_ys + (size_t)(j0 + lrow) * DD + lseg;

    float acc[8][8];
#pragma unroll
    for (int m = 0; m < 8; m++)
#pragma unroll
        for (int n = 0; n < 8; n++) acc[m][n] = 0.0f;

    for (int k0 = 0; k0 < DD; k0 += 8) {
        float4 av = *(const float4*)(Ab + k0);
        float4 bv = *(const float4*)(Bb + k0);
        As[lseg + 0][lrow] = av.x; As[lseg + 1][lrow] = av.y;
        As[lseg + 2][lrow] = av.z; As[lseg + 3][lrow] = av.w;
        Bs[lseg + 0][lrow] = bv.x; Bs[lseg + 1][lrow] = bv.y;
        Bs[lseg + 2][lrow] = bv.z; Bs[lseg + 3][lrow] = bv.w;
        __syncthreads();
#pragma unroll
        for (int kk = 0; kk < 8; kk++) {
            float ra[8], rb[8];
            *(float4*)(ra)     = *(const float4*)&As[kk][ty * 8];
            *(float4*)(ra + 4) = *(const float4*)&As[kk][ty * 8 + 4];
            *(float4*)(rb)     = *(const float4*)&Bs[kk][tx * 8];
            *(float4*)(rb + 4) = *(const float4*)&Bs[kk][tx * 8 + 4];
#pragma unroll
            for (int m = 0; m < 8; m++)
#pragma unroll
                for (int n = 0; n < 8; n++)
                    acc[m][n] = fmaf(ra[m], rb[n], acc[m][n]);
        }
        __syncthreads();
    }

    float xnr[8], ynr[8];
#pragma unroll
    for (int m = 0; m < 8; m++) xnr[m] = d_xn[i0 + ty * 8 + m];
#pragma unroll
    for (int n = 0; n < 8; n++) ynr[n] = d_yn[j0 + tx * 8 + n];

    float cmax = 0.0f;
#pragma unroll
    for (int m = 0; m < 8; m++) {
        int i = i0 + ty * 8 + m;
        float* Crow = d_C + (size_t)i * MM + j0 + tx * 8;
#pragma unroll
        for (int n = 0; n < 8; n++) {
            float c = fmaxf(xnr[m] + ynr[n] - 2.0f * acc[m][n], 0.0f);
            Crow[n] = c;
            cmax = fmaxf(cmax, c);
        }
    }
    redm[tid] = cmax;
    __syncthreads();
    for (int s = 128; s > 0; s >>= 1) {
        if (tid < s) redm[tid] = fmaxf(redm[tid], redm[tid + s]);
        __syncthreads();
    }
    if (tid == 0) atomicMax(&d_cmax_bits, __float_as_int(redm[0]));
}

// ---------------- K = exp(-10 * C / cmax) ----------------
__global__ void expk_kernel() {
    float cmax = __int_as_float(d_cmax_bits);
    float scale = -10.0f / cmax;
    int idx = blockIdx.x * blockDim.x + threadIdx.x;
    const float4* C4 = (const float4*)d_C;
    float4* K4 = (float4*)d_Km;
    float4 c = C4[idx];
    float4 k;
    k.x = expf(c.x * scale);
    k.y = expf(c.y * scale);
    k.z = expf(c.z * scale);
    k.w = expf(c.w * scale);
    K4[idx] = k;
}

// ---------------- persistent Sinkhorn (100 iters, 3 grid barriers / iter) ----------------
__device__ __forceinline__ void grid_bar(unsigned int gen) {
    __syncthreads();
    if (threadIdx.x == 0) {
        __threadfence();
        unsigned int t = atomicAdd(&d_bar_arrive, 1u) + 1u;
        if (t == gen * (unsigned int)gridDim.x) {
            atomicExch(&d_bar_release, gen);
        } else {
            volatile unsigned int* rel = &d_bar_release;
            while (*rel < gen) __nanosleep(64);
        }
        __threadfence();
    }
    __syncthreads();
}

__global__ __launch_bounds__(SINK_THREADS, 1) void sinkhorn_kernel() {
    __shared__ float sv[MM];  // 8 KB
    const float a  = 1.0f / NN;
    const float b  = 1.0f / MM;
    const float fi = (float)(0.5 / 0.6);  // tau / (tau + reg)

    int tid = threadIdx.x;
    int bid = blockIdx.x;
    int nb  = gridDim.x;
    int warp = tid >> 5, lane = tid & 31;
    unsigned int gen = 0;

    for (int it = 0; it < ITERS; ++it) {
        // stage v into shared (written cross-SM last iter -> bypass L1)
        for (int j = tid; j < MM; j += SINK_THREADS) sv[j] = __ldcg(&d_v[j]);
        __syncthreads();

        // Phase A: Kv -> u.  One warp per row; each block owns rows == bid (mod nb)
        const float4* sv4 = (const float4*)sv;
        for (int row = bid + nb * warp; row < NN; row += nb * 32) {
            const float4* Kr = (const float4*)(d_Km + (size_t)row * MM);
            float acc = 0.0f;
#pragma unroll 4
            for (int q = lane; q < MM / 4; q += 32) {
                float4 kk = Kr[q];
                float4 vv = sv4[q];
                acc = fmaf(kk.x, vv.x, acc);
                acc = fmaf(kk.y, vv.y, acc);
                acc = fmaf(kk.z, vv.z, acc);
                acc = fmaf(kk.w, vv.w, acc);
            }
#pragma unroll
            for (int o = 16; o > 0; o >>= 1) acc += __shfl_xor_sync(0xffffffffu, acc, o);
            if (lane == 0) d_u[row] = powf(a / acc, fi);
        }
        gen++; grid_bar(gen);

        // Phase B: K^T u partial sums (same row set per block), atomic into KTu
        float acc0 = 0.0f, acc1 = 0.0f;
        for (int row = bid; row < NN; row += nb) {
            float uu = __ldcg(&d_u[row]);
            float2 kk = ((const float2*)(d_Km + (size_t)row * MM))[tid];
            acc0 = fmaf(kk.x, uu, acc0);
            acc1 = fmaf(kk.y, uu, acc1);
        }
        atomicAdd(&d_KTu[2 * tid],     acc0);
        atomicAdd(&d_KTu[2 * tid + 1], acc1);
        gen++; grid_bar(gen);

        // Phase C: v update computed ONCE globally (2048 threads), zero KTu in place
        if (bid < 2) {
            int j = bid * SINK_THREADS + tid;
            float kt = __ldcg(&d_KTu[j]);
            d_v[j]   = powf(b / kt, fi);
            d_KTu[j] = 0.0f;
        }
        gen++; grid_bar(gen);
    }
}

// ---------------- flow = u*K*v, write transposed, accumulate dist = sum(C*flow) ----------------
__global__ __launch_bounds__(1024) void flow_kernel(float* __restrict__ out) {
    __shared__ float tile[32][33];
    __shared__ float wsum[32];
    int tx = threadIdx.x, ty = threadIdx.y;
    int j0 = blockIdx.x * 32;  // M dim
    int i0 = blockIdx.y * 32;  // N dim
    int i = i0 + ty, j = j0 + tx;
    size_t idx = (size_t)i * MM + j;

    float k = d_Km[idx];
    float f = d_u[i] * k * d_v[j];
    float c = d_C[idx];
    tile[ty][tx] = f;

    float contrib = c * f;
#pragma unroll
    for (int o = 16; o > 0; o >>= 1) contrib += __shfl_xor_sync(0xffffffffu, contrib, o);
    if (tx == 0) wsum[ty] = contrib;  // warp == ty for blockDim (32,32)
    __syncthreads();
    if (ty == 0) {
        float s = wsum[tx];
#pragma unroll
        for (int o = 16; o > 0; o >>= 1) s += __shfl_xor_sync(0xffffffffu, s, o);
        if (tx == 0) atomicAdd(&d_dist, (double)s);
    }
    // transposed write: out is flow.T [M, N]
    out[(size_t)(j0 + ty) * NN + (i0 + tx)] = tile[tx][ty];
}

__global__ void dist_kernel(float* __restrict__ out, int out_size) {
    int base = NN * MM;
    int j = base + blockIdx.x * blockDim.x + threadIdx.x;
    if (j < out_size) out[j] = (float)d_dist;
}

// ---------------- launch ----------------
extern "C" void kernel_launch(void* const* d_in, const int* in_sizes, int n_in,
                              void* d_out, int out_size) {
    const float* x = (const float*)d_in[0];
    const float* y = (const float*)d_in[1];
    // defensive: x must be the 4096-row tensor
    if (n_in >= 2 && in_sizes[0] == MM * DD && in_sizes[1] == NN * DD) {
        const float* t = x; x = y; y = t;
    }
    float* out = (float*)d_out;

    init_kernel<<<2, 1024>>>();
    prep_kernel<<<NN + MM, 256>>>(x, y);
    gemm_cost_kernel<<<dim3(MM / 128, NN / 128), 256>>>();
    expk_kernel<<<(NN * MM / 4) / 1024, 1024>>>();
    sinkhorn_kernel<<<SINK_BLOCKS, SINK_THREADS>>>();
    flow_kernel<<<dim3(MM / 32, NN / 32), dim3(32, 32)>>>(out);

    int base = NN * MM;
    if (out_size > base) {
        int rem = out_size - base;
        dist_kernel<<<(rem + 255) / 256, 256>>>(out, out_size);
    }
}

// round 3
// speedup vs baseline: 1.0808x; 1.0808x over previous
#include <cuda_runtime.h>
#include <cuda_fp16.h>

#define NN 4096
#define MM 2048
#define DD 1024
#define ITERS 100
#define SINK_BLOCKS 148
#define SINK_THREADS 1024

// ---------------- static scratch (no allocations allowed) ----------------
__device__ float d_xs[NN * DD];       // shifted x
__device__ float d_ys[MM * DD];       // shifted y
__device__ float d_xn[NN];            // row sq-norms of shifted x
__device__ float d_yn[MM];
__device__ float d_C[NN * MM];        // cost matrix (fp32, 33.5MB)
__device__ __half d_Kh[NN * MM];      // Gibbs kernel  (fp16 row-major, 16.8MB)
__device__ __half d_KhT[MM * NN];     // Gibbs kernel transposed (fp16, 16.8MB)
__device__ float d_u[NN];
__device__ float d_v[MM];
__device__ int d_cmax_bits;
__device__ unsigned int d_bar_arrive;
__device__ unsigned int d_bar_release;
__device__ double d_dist;

// ---------------- init: reset all cross-launch state (graph-replay safe) ----------------
__global__ void init_kernel() {
    int j = blockIdx.x * blockDim.x + threadIdx.x;
    if (j < MM) d_v[j] = 1.0f / MM;   // v0 = 1/m
    if (j == 0) {
        d_cmax_bits   = 0;
        d_bar_arrive  = 0;
        d_bar_release = 0;
        d_dist        = 0.0;
    }
}

// ---------------- row-min shift + squared norms ----------------
__global__ __launch_bounds__(256) void prep_kernel(const float* __restrict__ x,
                                                   const float* __restrict__ y) {
    __shared__ float red[256];
    int b = blockIdx.x;
    const float* src;
    float* dst;
    float* nrm;
    int row;
    if (b < NN) { row = b;       src = x + (size_t)row * DD; dst = d_xs + (size_t)row * DD; nrm = d_xn; }
    else        { row = b - NN;  src = y + (size_t)row * DD; dst = d_ys + (size_t)row * DD; nrm = d_yn; }

    int tid = threadIdx.x;
    float vals[4];
    float vmin = 3.4e38f;
#pragma unroll
    for (int i = 0; i < 4; i++) {
        vals[i] = src[tid + i * 256];
        vmin = fminf(vmin, vals[i]);
    }
    red[tid] = vmin;
    __syncthreads();
    for (int s = 128; s > 0; s >>= 1) {
        if (tid < s) red[tid] = fminf(red[tid], red[tid + s]);
        __syncthreads();
    }
    vmin = red[0];
    __syncthreads();

    float ss = 0.0f;
#pragma unroll
    for (int i = 0; i < 4; i++) {
        float t = vals[i] - vmin;
        dst[tid + i * 256] = t;
        ss += t * t;
    }
    red[tid] = ss;
    __syncthreads();
    for (int s = 128; s > 0; s >>= 1) {
        if (tid < s) red[tid] += red[tid + s];
        __syncthreads();
    }
    if (tid == 0) nrm[row] = red[0];
}

// ---------------- fp32 SGEMM (G = xs @ ys^T) fused with C = max(xn+yn-2G, 0) + global max
// inner loop uses Blackwell packed fma.rn.f32x2 (2x fp32 FMA rate) ----------------
__global__ __launch_bounds__(256) void gemm_cost_kernel() {
    __shared__ float As[8][128];
    __shared__ float Bs[8][128];
    __shared__ float redm[256];

    int j0 = blockIdx.x * 128;  // M dim
    int i0 = blockIdx.y * 128;  // N dim
    int tid = threadIdx.x;
    int tx = tid & 15, ty = tid >> 4;
    int lrow = tid >> 1;
    int lseg = (tid & 1) * 4;

    const float* Ab = d_xs + (size_t)(i0 + lrow) * DD + lseg;
    const float* Bb = d_ys + (size_t)(j0 + lrow) * DD + lseg;

    unsigned long long acc2[8][4];
#pragma unroll
    for (int m = 0; m < 8; m++)
#pragma unroll
        for (int n = 0; n < 4; n++) acc2[m][n] = 0ull;

    for (int k0 = 0; k0 < DD; k0 += 8) {
        float4 av = *(const float4*)(Ab + k0);
        float4 bv = *(const float4*)(Bb + k0);
        As[lseg + 0][lrow] = av.x; As[lseg + 1][lrow] = av.y;
        As[lseg + 2][lrow] = av.z; As[lseg + 3][lrow] = av.w;
        Bs[lseg + 0][lrow] = bv.x; Bs[lseg + 1][lrow] = bv.y;
        Bs[lseg + 2][lrow] = bv.z; Bs[lseg + 3][lrow] = bv.w;
        __syncthreads();
#pragma unroll
        for (int kk = 0; kk < 8; kk++) {
            float ra[8];
            unsigned long long rb2[4];
            *(float4*)(ra)     = *(const float4*)&As[kk][ty * 8];
            *(float4*)(ra + 4) = *(const float4*)&As[kk][ty * 8 + 4];
            *(float4*)(&rb2[0]) = *(const float4*)&Bs[kk][tx * 8];
            *(float4*)(&rb2[2]) = *(const float4*)&Bs[kk][tx * 8 + 4];
#pragma unroll
            for (int m = 0; m < 8; m++) {
                unsigned long long am;
                unsigned int rai = __float_as_uint(ra[m]);
                asm("mov.b64 %0, {%1, %1};" : "=l"(am) : "r"(rai));
#pragma unroll
                for (int n = 0; n < 4; n++)
                    asm("fma.rn.f32x2 %0, %1, %2, %0;"
                        : "+l"(acc2[m][n]) : "l"(am), "l"(rb2[n]));
            }
        }
        __syncthreads();
    }

    float xnr[8], ynr[8];
#pragma unroll
    for (int m = 0; m < 8; m++) xnr[m] = d_xn[i0 + ty * 8 + m];
#pragma unroll
    for (int n = 0; n < 8; n++) ynr[n] = d_yn[j0 + tx * 8 + n];

    float cmax = 0.0f;
#pragma unroll
    for (int m = 0; m < 8; m++) {
        int i = i0 + ty * 8 + m;
        float* Crow = d_C + (size_t)i * MM + j0 + tx * 8;
#pragma unroll
        for (int n = 0; n < 4; n++) {
            unsigned int lo, hi;
            asm("mov.b64 {%0, %1}, %2;" : "=r"(lo), "=r"(hi) : "l"(acc2[m][n]));
            float g0 = __uint_as_float(lo);
            float g1 = __uint_as_float(hi);
            float c0 = fmaxf(xnr[m] + ynr[2 * n]     - 2.0f * g0, 0.0f);
            float c1 = fmaxf(xnr[m] + ynr[2 * n + 1] - 2.0f * g1, 0.0f);
            Crow[2 * n]     = c0;
            Crow[2 * n + 1] = c1;
            cmax = fmaxf(cmax, fmaxf(c0, c1));
        }
    }
    redm[tid] = cmax;
    __syncthreads();
    for (int s = 128; s > 0; s >>= 1) {
        if (tid < s) redm[tid] = fmaxf(redm[tid], redm[tid + s]);
        __syncthreads();
    }
    if (tid == 0) atomicMax(&d_cmax_bits, __float_as_int(redm[0]));
}

// ---------------- Kh = fp16(exp(-10*C/cmax)), plus transposed copy KhT ----------------
__global__ __launch_bounds__(256) void expk_tr_kernel() {
    __shared__ __half t[64][72];
    float cmax = __int_as_float(d_cmax_bits);
    float s = -10.0f / cmax;
    int j0 = blockIdx.x * 64;  // M dim
    int i0 = blockIdx.y * 64;  // N dim
    int tx = threadIdx.x & 15;   // col group (4 cols each)
    int ty = threadIdx.x >> 4;   // 16 rows per pass

#pragma unroll
    for (int p = 0; p < 4; p++) {
        int r = p * 16 + ty;
        int i = i0 + r;
        float4 c = *(const float4*)(d_C + (size_t)i * MM + j0 + tx * 4);
        __half h0 = __float2half_rn(expf(c.x * s));
        __half h1 = __float2half_rn(expf(c.y * s));
        __half h2 = __float2half_rn(expf(c.z * s));
        __half h3 = __float2half_rn(expf(c.w * s));
        __half2 p01 = __halves2half2(h0, h1);
        __half2 p23 = __halves2half2(h2, h3);
        __half2* dst = (__half2*)(d_Kh + (size_t)i * MM + j0 + tx * 4);
        dst[0] = p01;
        dst[1] = p23;
        t[r][tx * 4 + 0] = h0; t[r][tx * 4 + 1] = h1;
        t[r][tx * 4 + 2] = h2; t[r][tx * 4 + 3] = h3;
    }
    __syncthreads();
#pragma unroll
    for (int p = 0; p < 4; p++) {
        int jr = p * 16 + ty;
        int j = j0 + jr;
        __half2 q01 = __halves2half2(t[tx * 4 + 0][jr], t[tx * 4 + 1][jr]);
        __half2 q23 = __halves2half2(t[tx * 4 + 2][jr], t[tx * 4 + 3][jr]);
        __half2* dst = (__half2*)(d_KhT + (size_t)j * NN + i0 + tx * 4);
        dst[0] = q01;
        dst[1] = q23;
    }
}

// ---------------- persistent Sinkhorn (100 iters, 2 grid barriers / iter, fp16 K) ----------------
__device__ __forceinline__ void grid_bar(unsigned int gen) {
    __syncthreads();
    if (threadIdx.x == 0) {
        __threadfence();
        unsigned int t = atomicAdd(&d_bar_arrive, 1u) + 1u;
        if (t == gen * (unsigned int)gridDim.x) {
            atomicExch(&d_bar_release, gen);
        } else {
            volatile unsigned int* rel = &d_bar_release;
            while (*rel < gen) __nanosleep(64);
        }
        __threadfence();
    }
    __syncthreads();
}

__global__ __launch_bounds__(SINK_THREADS, 1) void sinkhorn_kernel() {
    __shared__ float stage[NN];  // 16KB: holds v (first 2048) in phase A, u (4096) in phase B
    const float a  = 1.0f / NN;
    const float b  = 1.0f / MM;
    const float fi = (float)(0.5 / 0.6);  // tau / (tau + reg)

    int tid = threadIdx.x;
    int bid = blockIdx.x;
    int warp = tid >> 5, lane = tid & 31;
    int gw = bid * 32 + warp;             // global warp id
    const int GW = SINK_BLOCKS * 32;      // 4736
    unsigned int gen = 0;

    for (int it = 0; it < ITERS; ++it) {
        // stage v (cross-SM data -> L2 reads)
        for (int j = tid; j < MM; j += SINK_THREADS) stage[j] = __ldcg(&d_v[j]);
        __syncthreads();

        // Phase A: u[i] = (a / sum_j K[i,j] v[j])^fi   (one warp per row)
        const float4* sv4 = (const float4*)stage;
        for (int r = gw; r < NN; r += GW) {
            const uint4* Kr = (const uint4*)(d_Kh + (size_t)r * MM);
            float acc = 0.0f;
#pragma unroll
            for (int q = 0; q < 8; q++) {
                uint4 kk = Kr[q * 32 + lane];
                int base2 = (q * 32 + lane) * 2;
                float4 v0 = sv4[base2];
                float4 v1 = sv4[base2 + 1];
                float2 h;
                h = __half22float2(*(__half2*)&kk.x);
                acc = fmaf(h.x, v0.x, acc); acc = fmaf(h.y, v0.y, acc);
                h = __half22float2(*(__half2*)&kk.y);
                acc = fmaf(h.x, v0.z, acc); acc = fmaf(h.y, v0.w, acc);
                h = __half22float2(*(__half2*)&kk.z);
                acc = fmaf(h.x, v1.x, acc); acc = fmaf(h.y, v1.y, acc);
                h = __half22float2(*(__half2*)&kk.w);
                acc = fmaf(h.x, v1.z, acc); acc = fmaf(h.y, v1.w, acc);
            }
#pragma unroll
            for (int o = 16; o > 0; o >>= 1) acc += __shfl_xor_sync(0xffffffffu, acc, o);
            if (lane == 0) __stcg(&d_u[r], powf(a / acc, fi));
        }
        gen++; grid_bar(gen);

        // stage u
        for (int j = tid; j < NN; j += SINK_THREADS) stage[j] = __ldcg(&d_u[j]);
        __syncthreads();

        // Phase B: v[j] = (b / sum_i K[i,j] u[i])^fi  via transposed rows (one warp per col)
        const float4* su4 = (const float4*)stage;
        for (int r = gw; r < MM; r += GW) {
            const uint4* Kr = (const uint4*)(d_KhT + (size_t)r * NN);
            float acc = 0.0f;
#pragma unroll
            for (int q = 0; q < 16; q++) {
                uint4 kk = Kr[q * 32 + lane];
                int base2 = (q * 32 + lane) * 2;
                float4 u0 = su4[base2];
                float4 u1 = su4[base2 + 1];
                float2 h;
                h = __half22float2(*(__half2*)&kk.x);
                acc = fmaf(h.x, u0.x, acc); acc = fmaf(h.y, u0.y, acc);
                h = __half22float2(*(__half2*)&kk.y);
                acc = fmaf(h.x, u0.z, acc); acc = fmaf(h.y, u0.w, acc);
                h = __half22float2(*(__half2*)&kk.z);
                acc = fmaf(h.x, u1.x, acc); acc = fmaf(h.y, u1.y, acc);
                h = __half22float2(*(__half2*)&kk.w);
                acc = fmaf(h.x, u1.z, acc); acc = fmaf(h.y, u1.w, acc);
            }
#pragma unroll
            for (int o = 16; o > 0; o >>= 1) acc += __shfl_xor_sync(0xffffffffu, acc, o);
            if (lane == 0) __stcg(&d_v[r], powf(b / acc, fi));
        }
        gen++; grid_bar(gen);
    }
}

// ---------------- flow = u*K*v (K recomputed fp32), write transposed, dist = sum(C*flow) ----------------
__global__ __launch_bounds__(1024) void flow_kernel(float* __restrict__ out) {
    __shared__ float tile[32][33];
    __shared__ float wsum[32];
    float cmax = __int_as_float(d_cmax_bits);
    float scale = -10.0f / cmax;
    int tx = threadIdx.x, ty = threadIdx.y;
    int j0 = blockIdx.x * 32;  // M dim
    int i0 = blockIdx.y * 32;  // N dim
    int i = i0 + ty, j = j0 + tx;
    size_t idx = (size_t)i * MM + j;

    float c = d_C[idx];
    float k = expf(c * scale);
    float f = d_u[i] * k * d_v[j];
    tile[ty][tx] = f;

    float contrib = c * f;
#pragma unroll
    for (int o = 16; o > 0; o >>= 1) contrib += __shfl_xor_sync(0xffffffffu, contrib, o);
    if (tx == 0) wsum[ty] = contrib;
    __syncthreads();
    if (ty == 0) {
        float s = wsum[tx];
#pragma unroll
        for (int o = 16; o > 0; o >>= 1) s += __shfl_xor_sync(0xffffffffu, s, o);
        if (tx == 0) atomicAdd(&d_dist, (double)s);
    }
    // transposed write: out is flow.T [M, N]
    out[(size_t)(j0 + ty) * NN + (i0 + tx)] = tile[tx][ty];
}

__global__ void dist_kernel(float* __restrict__ out, int out_size) {
    int base = NN * MM;
    int j = base + blockIdx.x * blockDim.x + threadIdx.x;
    if (j < out_size) out[j] = (float)d_dist;
}

// ---------------- launch ----------------
extern "C" void kernel_launch(void* const* d_in, const int* in_sizes, int n_in,
                              void* d_out, int out_size) {
    const float* x = (const float*)d_in[0];
    const float* y = (const float*)d_in[1];
    if (n_in >= 2 && in_sizes[0] == MM * DD && in_sizes[1] == NN * DD) {
        const float* t = x; x = y; y = t;
    }
    float* out = (float*)d_out;

    init_kernel<<<2, 1024>>>();
    prep_kernel<<<NN + MM, 256>>>(x, y);
    gemm_cost_kernel<<<dim3(MM / 128, NN / 128), 256>>>();
    expk_tr_kernel<<<dim3(MM / 64, NN / 64), 256>>>();
    sinkhorn_kernel<<<SINK_BLOCKS, SINK_THREADS>>>();
    flow_kernel<<<dim3(MM / 32, NN / 32), dim3(32, 32)>>>(out);

    int base = NN * MM;
    if (out_size > base) {
        int rem = out_size - base;
        dist_kernel<<<(rem + 255) / 256, 256>>>(out, out_size);
    }
}

// round 8
// speedup vs baseline: 1.6008x; 1.4811x over previous
#include <cuda_runtime.h>
#include <cuda_fp16.h>
#include <cuda_bf16.h>
#include <cstdint>

#define NN 4096
#define MM 2048
#define DD 1024
#define ITERS 100
#define SINK_BLOCKS 148
#define SINK_THREADS 1024

// ---------------- static scratch (no allocations allowed) ----------------
__device__ __nv_bfloat16 d_xhi[NN * DD];
__device__ __nv_bfloat16 d_xlo[NN * DD];
__device__ __nv_bfloat16 d_yhi[MM * DD];
__device__ __nv_bfloat16 d_ylo[MM * DD];
__device__ float d_xn[NN];
__device__ float d_yn[MM];
__device__ float d_C[NN * MM];        // cost matrix (fp32, 33.5MB)
__device__ __half d_Kh[NN * MM];      // Gibbs kernel (fp16 row-major)
__device__ __half d_KhT[MM * NN];     // Gibbs kernel transposed
__device__ float d_u[NN];
__device__ float d_v[MM];
__device__ int d_cmax_bits;
__device__ unsigned int d_bar_arrive;
__device__ unsigned int d_bar_release;
__device__ double d_dist;

// ---------------- helpers ----------------
__device__ __forceinline__ uint32_t smem_u32(const void* p) {
    uint32_t a;
    asm("{ .reg .u64 t; cvta.to.shared.u64 t, %1; cvt.u32.u64 %0, t; }" : "=r"(a) : "l"(p));
    return a;
}

#define LDSM4(r, addr) \
    asm volatile("ldmatrix.sync.aligned.m8n8.x4.shared.b16 {%0,%1,%2,%3}, [%4];" \
                 : "=r"((r)[0]), "=r"((r)[1]), "=r"((r)[2]), "=r"((r)[3]) : "r"(addr))

#define MMA16816(d, a, b0, b1) \
    asm volatile("mma.sync.aligned.m16n8k16.row.col.f32.bf16.bf16.f32 " \
                 "{%0,%1,%2,%3},{%4,%5,%6,%7},{%8,%9},{%0,%1,%2,%3};" \
                 : "+f"((d)[0]), "+f"((d)[1]), "+f"((d)[2]), "+f"((d)[3]) \
                 : "r"((a)[0]), "r"((a)[1]), "r"((a)[2]), "r"((a)[3]), "r"(b0), "r"(b1))

// ---------------- init ----------------
__global__ void init_kernel() {
    int j = blockIdx.x * blockDim.x + threadIdx.x;
    if (j < MM) d_v[j] = 1.0f / MM;
    if (j == 0) {
        d_cmax_bits = 0; d_bar_arrive = 0; d_bar_release = 0; d_dist = 0.0;
    }
}

// ---------------- row-min shift + squared norms + bf16 hi/lo split ----------------
__global__ __launch_bounds__(256) void prep_kernel(const float* __restrict__ x,
                                                   const float* __restrict__ y) {
    __shared__ float red[256];
    int b = blockIdx.x;
    const float* src;
    __nv_bfloat16 *hdst, *ldst;
    float* nrm;
    int row;
    if (b < NN) { row = b;      src = x + (size_t)row * DD; hdst = d_xhi + (size_t)row * DD; ldst = d_xlo + (size_t)row * DD; nrm = d_xn; }
    else        { row = b - NN; src = y + (size_t)row * DD; hdst = d_yhi + (size_t)row * DD; ldst = d_ylo + (size_t)row * DD; nrm = d_yn; }

    int tid = threadIdx.x;
    float vals[4];
    float vmin = 3.4e38f;
#pragma unroll
    for (int i = 0; i < 4; i++) {
        vals[i] = src[tid + i * 256];
        vmin = fminf(vmin, vals[i]);
    }
    red[tid] = vmin;
    __syncthreads();
    for (int s = 128; s > 0; s >>= 1) {
        if (tid < s) red[tid] = fminf(red[tid], red[tid + s]);
        __syncthreads();
    }
    vmin = red[0];
    __syncthreads();

    float ss = 0.0f;
#pragma unroll
    for (int i = 0; i < 4; i++) {
        float t = vals[i] - vmin;
        __nv_bfloat16 h = __float2bfloat16(t);
        float hf = __bfloat162float(h);
        hdst[tid + i * 256] = h;
        ldst[tid + i * 256] = __float2bfloat16(t - hf);
        ss += t * t;
    }
    red[tid] = ss;
    __syncthreads();
    for (int s = 128; s > 0; s >>= 1) {
        if (tid < s) red[tid] += red[tid + s];
        __syncthreads();
    }
    if (tid == 0) nrm[row] = red[0];
}

// ---------------- bf16-split GEMM via mma.sync (HMMA) + cost epilogue ----------------
// CTA: 128x128 tile. 8 warps as 2(m)x4(n), warp tile 64x32.
// K chunk = 32 (2 k16 steps). smem row stride 80B (40 bf16) -> conflict-free ldmatrix.
// D = Xhi*Yhi^T + Xhi*Ylo^T + Xlo*Yhi^T  (fp32 accum)
#define KC 32
#define NCHUNK (DD / KC)            // 32
#define ROWSTR 80                   // bytes per smem row (32 bf16 data + 8 pad)
#define MAT_B (128 * ROWSTR)        // 10240
#define STAGE_B (4 * MAT_B)         // 40960
#define GEMM_SMEM (2 * STAGE_B)     // 81920

__global__ __launch_bounds__(256) void gemm_cost_kernel() {
    extern __shared__ char smem[];
    uint32_t sb = smem_u32(smem);

    int tid = threadIdx.x;
    int wid = tid >> 5, lane = tid & 31;
    int j0 = blockIdx.x * 128;  // y rows (output cols)
    int i0 = blockIdx.y * 128;  // x rows (output rows)

    // ---- gmem load mapping: 64 threads per matrix, coalesced 64B rows ----
    int mat  = tid >> 6;        // 0:Ah 1:Al 2:Bh 3:Bl
    int w    = tid & 63;
    int colu = w & 3;           // uint4 col within 32-col chunk
    int rb   = w >> 2;          // row base 0..15 (rows rb + q*16)
    const __nv_bfloat16* gp = (mat == 0) ? d_xhi : (mat == 1) ? d_xlo
                            : (mat == 2) ? d_yhi : d_ylo;
    int rbase = (mat < 2) ? i0 : j0;
    const uint4* g4 = (const uint4*)gp + (size_t)rbase * (DD / 8);
    char* smat = smem + mat * MAT_B;

    // ---- ldmatrix address offsets (within a stage) ----
    int wm = wid >> 2, wn = wid & 3;
    int aoff[4], boff[2];
#pragma unroll
    for (int mt = 0; mt < 4; mt++)
        aoff[mt] = (wm * 64 + mt * 16 + (lane & 15)) * ROWSTR + (lane >> 4) * 16;
#pragma unroll
    for (int np = 0; np < 2; np++)
        boff[np] = (wn * 32 + np * 16 + (lane & 7) + ((lane >> 4) & 1) * 8) * ROWSTR
                 + ((lane >> 3) & 1) * 16;

    float acc[4][4][4];
#pragma unroll
    for (int mt = 0; mt < 4; mt++)
#pragma unroll
        for (int nt = 0; nt < 4; nt++)
#pragma unroll
            for (int r = 0; r < 4; r++) acc[mt][nt][r] = 0.0f;

    // ---- prologue: chunk 0 -> stage 0 ----
    {
        uint4 v[8];
#pragma unroll
        for (int q = 0; q < 8; q++)
            v[q] = g4[(size_t)(rb + q * 16) * (DD / 8) + colu];
#pragma unroll
        for (int q = 0; q < 8; q++)
            *(uint4*)(smat + (rb + q * 16) * ROWSTR + colu * 16) = v[q];
    }
    __syncthreads();

    for (int kc = 0; kc < NCHUNK; kc++) {
        int p = kc & 1;
        uint4 v[8];
        if (kc + 1 < NCHUNK) {
#pragma unroll
            for (int q = 0; q < 8; q++)
                v[q] = g4[(size_t)(rb + q * 16) * (DD / 8) + (kc + 1) * 4 + colu];
        }

        uint32_t st = sb + p * STAGE_B;
#pragma unroll
        for (int ks = 0; ks < 2; ks++) {
            uint32_t ah[4][4], al[4][4], bh[2][4], bl[2][4];
#pragma unroll
            for (int mt = 0; mt < 4; mt++) {
                LDSM4(ah[mt], st + aoff[mt] + ks * 32);
                LDSM4(al[mt], st + MAT_B + aoff[mt] + ks * 32);
            }
#pragma unroll
            for (int np = 0; np < 2; np++) {
                LDSM4(bh[np], st + 2 * MAT_B + boff[np] + ks * 32);
                LDSM4(bl[np], st + 3 * MAT_B + boff[np] + ks * 32);
            }
#pragma unroll
            for (int mt = 0; mt < 4; mt++)
#pragma unroll
                for (int nt = 0; nt < 4; nt++) {
                    int np = nt >> 1, s = (nt & 1) * 2;
                    MMA16816(acc[mt][nt], ah[mt], bh[np][s], bh[np][s + 1]);
                    MMA16816(acc[mt][nt], ah[mt], bl[np][s], bl[np][s + 1]);
                    MMA16816(acc[mt][nt], al[mt], bh[np][s], bh[np][s + 1]);
                }
        }

        if (kc + 1 < NCHUNK) {
            char* sdst = smem + (p ^ 1) * STAGE_B + mat * MAT_B;
#pragma unroll
            for (int q = 0; q < 8; q++)
                *(uint4*)(sdst + (rb + q * 16) * ROWSTR + colu * 16) = v[q];
        }
        __syncthreads();
    }

    // ---- epilogue: C = max(xn + yn - 2G, 0) + global max ----
    float cmax = 0.0f;
    int mrow = lane >> 2;            // 0..7
    int ncol = (lane & 3) * 2;       // 0,2,4,6
#pragma unroll
    for (int mt = 0; mt < 4; mt++) {
        int i_a = i0 + wm * 64 + mt * 16 + mrow;
        int i_b = i_a + 8;
        float xa = d_xn[i_a], xb = d_xn[i_b];
#pragma unroll
        for (int nt = 0; nt < 4; nt++) {
            int j = j0 + wn * 32 + nt * 8 + ncol;
            float y0 = d_yn[j], y1 = d_yn[j + 1];
            float c0 = fmaxf(xa + y0 - 2.0f * acc[mt][nt][0], 0.0f);
            float c1 = fmaxf(xa + y1 - 2.0f * acc[mt][nt][1], 0.0f);
            float c2 = fmaxf(xb + y0 - 2.0f * acc[mt][nt][2], 0.0f);
            float c3 = fmaxf(xb + y1 - 2.0f * acc[mt][nt][3], 0.0f);
            *(float2*)(d_C + (size_t)i_a * MM + j) = make_float2(c0, c1);
            *(float2*)(d_C + (size_t)i_b * MM + j) = make_float2(c2, c3);
            cmax = fmaxf(cmax, fmaxf(fmaxf(c0, c1), fmaxf(c2, c3)));
        }
    }
#pragma unroll
    for (int o = 16; o > 0; o >>= 1)
        cmax = fmaxf(cmax, __shfl_xor_sync(0xffffffffu, cmax, o));
    if (lane == 0) atomicMax(&d_cmax_bits, __float_as_int(cmax));
}

// ---------------- Kh = fp16(exp(-10*C/cmax)), plus transposed copy KhT ----------------
__global__ __launch_bounds__(256) void expk_tr_kernel() {
    __shared__ __half t[64][72];
    float cmax = __int_as_float(d_cmax_bits);
    float s = -10.0f / cmax;
    int j0 = blockIdx.x * 64;
    int i0 = blockIdx.y * 64;
    int tx = threadIdx.x & 15;
    int ty = threadIdx.x >> 4;

#pragma unroll
    for (int p = 0; p < 4; p++) {
        int r = p * 16 + ty;
        int i = i0 + r;
        float4 c = *(const float4*)(d_C + (size_t)i * MM + j0 + tx * 4);
        __half h0 = __float2half_rn(expf(c.x * s));
        __half h1 = __float2half_rn(expf(c.y * s));
        __half h2 = __float2half_rn(expf(c.z * s));
        __half h3 = __float2half_rn(expf(c.w * s));
        __half2* dst = (__half2*)(d_Kh + (size_t)i * MM + j0 + tx * 4);
        dst[0] = __halves2half2(h0, h1);
        dst[1] = __halves2half2(h2, h3);
        t[r][tx * 4 + 0] = h0; t[r][tx * 4 + 1] = h1;
        t[r][tx * 4 + 2] = h2; t[r][tx * 4 + 3] = h3;
    }
    __syncthreads();
#pragma unroll
    for (int p = 0; p < 4; p++) {
        int jr = p * 16 + ty;
        int j = j0 + jr;
        __half2* dst = (__half2*)(d_KhT + (size_t)j * NN + i0 + tx * 4);
        dst[0] = __halves2half2(t[tx * 4 + 0][jr], t[tx * 4 + 1][jr]);
        dst[1] = __halves2half2(t[tx * 4 + 2][jr], t[tx * 4 + 3][jr]);
    }
}

// ---------------- persistent Sinkhorn ----------------
__device__ __forceinline__ void grid_bar(unsigned int gen) {
    __syncthreads();
    if (threadIdx.x == 0) {
        __threadfence();
        unsigned int t = atomicAdd(&d_bar_arrive, 1u) + 1u;
        if (t == gen * (unsigned int)gridDim.x) {
            atomicExch(&d_bar_release, gen);
        } else {
            volatile unsigned int* rel = &d_bar_release;
            while (*rel < gen) __nanosleep(64);
        }
        __threadfence();
    }
    __syncthreads();
}

__global__ __launch_bounds__(SINK_THREADS, 1) void sinkhorn_kernel() {
    __shared__ float stage[NN];
    const float a  = 1.0f / NN;
    const float b  = 1.0f / MM;
    const float fi = (float)(0.5 / 0.6);

    int tid = threadIdx.x;
    int bid = blockIdx.x;
    int warp = tid >> 5, lane = tid & 31;
    int gw = bid + warp * SINK_BLOCKS;   // spread active warps across ALL SMs
    const int GW = SINK_BLOCKS * 32;
    unsigned int gen = 0;

    for (int it = 0; it < ITERS; ++it) {
        for (int j = tid; j < MM; j += SINK_THREADS) stage[j] = __ldcg(&d_v[j]);
        __syncthreads();

        const float4* sv4 = (const float4*)stage;
        for (int r = gw; r < NN; r += GW) {
            const uint4* Kr = (const uint4*)(d_Kh + (size_t)r * MM);
            float acc = 0.0f;
#pragma unroll
            for (int q = 0; q < 8; q++) {
                uint4 kk = Kr[q * 32 + lane];
                int b2 = (q * 32 + lane) * 2;
                float4 v0 = sv4[b2];
                float4 v1 = sv4[b2 + 1];
                float2 h;
                h = __half22float2(*(__half2*)&kk.x); acc = fmaf(h.x, v0.x, acc); acc = fmaf(h.y, v0.y, acc);
                h = __half22float2(*(__half2*)&kk.y); acc = fmaf(h.x, v0.z, acc); acc = fmaf(h.y, v0.w, acc);
                h = __half22float2(*(__half2*)&kk.z); acc = fmaf(h.x, v1.x, acc); acc = fmaf(h.y, v1.y, acc);
                h = __half22float2(*(__half2*)&kk.w); acc = fmaf(h.x, v1.z, acc); acc = fmaf(h.y, v1.w, acc);
            }
#pragma unroll
            for (int o = 16; o > 0; o >>= 1) acc += __shfl_xor_sync(0xffffffffu, acc, o);
            if (lane == 0) __stcg(&d_u[r], powf(a / acc, fi));
        }
        gen++; grid_bar(gen);

        for (int j = tid; j < NN; j += SINK_THREADS) stage[j] = __ldcg(&d_u[j]);
        __syncthreads();

        const float4* su4 = (const float4*)stage;
        for (int r = gw; r < MM; r += GW) {
            const uint4* Kr = (const uint4*)(d_KhT + (size_t)r * NN);
            float acc = 0.0f;
#pragma unroll
            for (int q = 0; q < 16; q++) {
                uint4 kk = Kr[q * 32 + lane];
                int b2 = (q * 32 + lane) * 2;
                float4 u0 = su4[b2];
                float4 u1 = su4[b2 + 1];
                float2 h;
                h = __half22float2(*(__half2*)&kk.x); acc = fmaf(h.x, u0.x, acc); acc = fmaf(h.y, u0.y, acc);
                h = __half22float2(*(__half2*)&kk.y); acc = fmaf(h.x, u0.z, acc); acc = fmaf(h.y, u0.w, acc);
                h = __half22float2(*(__half2*)&kk.z); acc = fmaf(h.x, u1.x, acc); acc = fmaf(h.y, u1.y, acc);
                h = __half22float2(*(__half2*)&kk.w); acc = fmaf(h.x, u1.z, acc); acc = fmaf(h.y, u1.w, acc);
            }
#pragma unroll
            for (int o = 16; o > 0; o >>= 1) acc += __shfl_xor_sync(0xffffffffu, acc, o);
            if (lane == 0) __stcg(&d_v[r], powf(b / acc, fi));
        }
        gen++; grid_bar(gen);
    }
}

// ---------------- flow = u*K*v (K recomputed fp32), write transposed, dist ----------------
__global__ __launch_bounds__(1024) void flow_kernel(float* __restrict__ out) {
    __shared__ float tile[32][33];
    __shared__ float wsum[32];
    float cmax = __int_as_float(d_cmax_bits);
    float scale = -10.0f / cmax;
    int tx = threadIdx.x, ty = threadIdx.y;
    int j0 = blockIdx.x * 32;
    int i0 = blockIdx.y * 32;
    int i = i0 + ty, j = j0 + tx;
    size_t idx = (size_t)i * MM + j;

    float c = d_C[idx];
    float k = expf(c * scale);
    float f = d_u[i] * k * d_v[j];
    tile[ty][tx] = f;

    float contrib = c * f;
#pragma unroll
    for (int o = 16; o > 0; o >>= 1) contrib += __shfl_xor_sync(0xffffffffu, contrib, o);
    if (tx == 0) wsum[ty] = contrib;
    __syncthreads();
    if (ty == 0) {
        float s = wsum[tx];
#pragma unroll
        for (int o = 16; o > 0; o >>= 1) s += __shfl_xor_sync(0xffffffffu, s, o);
        if (tx == 0) atomicAdd(&d_dist, (double)s);
    }
    out[(size_t)(j0 + ty) * NN + (i0 + tx)] = tile[tx][ty];
}

__global__ void dist_kernel(float* __restrict__ out, int out_size) {
    int base = NN * MM;
    int j = base + blockIdx.x * blockDim.x + threadIdx.x;
    if (j < out_size) out[j] = (float)d_dist;
}

// ---------------- launch ----------------
extern "C" void kernel_launch(void* const* d_in, const int* in_sizes, int n_in,
                              void* d_out, int out_size) {
    const float* x = (const float*)d_in[0];
    const float* y = (const float*)d_in[1];
    if (n_in >= 2 && in_sizes[0] == MM * DD && in_sizes[1] == NN * DD) {
        const float* t = x; x = y; y = t;
    }
    float* out = (float*)d_out;

    static int smem_set = 0;
    if (!smem_set) {
        cudaFuncSetAttribute(gemm_cost_kernel,
                             cudaFuncAttributeMaxDynamicSharedMemorySize, GEMM_SMEM);
        smem_set = 1;
    }

    init_kernel<<<2, 1024>>>();
    prep_kernel<<<NN + MM, 256>>>(x, y);
    gemm_cost_kernel<<<dim3(MM / 128, NN / 128), 256, GEMM_SMEM>>>();
    expk_tr_kernel<<<dim3(MM / 64, NN / 64), 256>>>();
    sinkhorn_kernel<<<SINK_BLOCKS, SINK_THREADS>>>();
    flow_kernel<<<dim3(MM / 32, NN / 32), dim3(32, 32)>>>(out);

    int base = NN * MM;
    if (out_size > base) {
        int rem = out_size - base;
        dist_kernel<<<(rem + 255) / 256, 256>>>(out, out_size);
    }
}